// round 13
// baseline (speedup 1.0000x reference)
#include <cuda_runtime.h>
#include <cstdint>

// Problem constants
namespace {
constexpr int B = 2, N = 2048, F = 768, H = 8, O = 256, HO = H * O;
constexpr float ALPHA = 0.2f;
constexpr int KC = 32;
constexpr int NCHUNK = N / KC;         // 64
// attn smem (floats): A bufs 2x2048, B bufs 2x8192, s1s 64, rzs 64
constexpr int ATT_A0 = 0;
constexpr int ATT_B0 = 4096;
constexpr int ATT_S1 = 20480;
constexpr int ATT_RZ = 20544;
constexpr int SMEM_ATTN_BYTES  = 20608 * 4;          // 82432 (x2 CTAs = 164 KB/SM)
constexpr int SMEM_GEMM2_BYTES = 16384 * 4;          // 65536 (hi/lo A, hi B)
constexpr int SMEM_GEMM1_BYTES = 12288 * 4;          // 49152 (hi only)
}

// ---------------- scratch (static device globals; no allocation) ----------
// ONLY referenced from device code (host-passing them hands over the host
// shadow symbol -> ATS silent corruption; round-6/8 bug).
__device__ float g_h  [(size_t)B * H * N * O];
__device__ float g_s1 [B * H * N];
__device__ float g_s2 [B * H * N];
__device__ float g_s2t[B * N * H];
__device__ float g_rz [B * H * N];
__device__ float g_x1 [(size_t)B * N * HO];
__device__ float g_h2 [(size_t)B * N * O];
__device__ float g_x2 [(size_t)B * N * O];
__device__ float g_s1b[B * N];
__device__ float g_s2b[B * N];
__device__ float g_rzb[B * N];

__device__ __forceinline__ float lrelu(float v) { return v > 0.f ? v : ALPHA * v; }
__device__ __forceinline__ float eluf(float v)  { return v > 0.f ? v : __expf(v) - 1.f; }

__device__ __forceinline__ float rna(float v) {
    uint32_t u; asm("cvt.rna.tf32.f32 %0, %1;" : "=r"(u) : "f"(v));
    return __uint_as_float(u);
}

__device__ __forceinline__ void mma4(float* c, const float4& a, const float2& b) {
    asm volatile(
        "mma.sync.aligned.m16n8k8.row.col.f32.tf32.tf32.f32 "
        "{%0,%1,%2,%3}, {%4,%5,%6,%7}, {%8,%9}, {%0,%1,%2,%3};"
        : "+f"(c[0]), "+f"(c[1]), "+f"(c[2]), "+f"(c[3])
        : "r"(__float_as_uint(a.x)), "r"(__float_as_uint(a.y)),
          "r"(__float_as_uint(a.z)), "r"(__float_as_uint(a.w)),
          "r"(__float_as_uint(b.x)), "r"(__float_as_uint(b.y)));
}

__device__ __forceinline__ uint32_t smem_u32(const void* p) {
    uint32_t a;
    asm("{ .reg .u64 t; cvta.to.shared.u64 t, %1; cvt.u32.u64 %0, t; }" : "=r"(a) : "l"(p));
    return a;
}
__device__ __forceinline__ void cp4(uint32_t dst, const float* src) {
    asm volatile("cp.async.ca.shared.global [%0], [%1], 4;" :: "r"(dst), "l"(src) : "memory");
}
#define CP_COMMIT() asm volatile("cp.async.commit_group;" ::: "memory")
#define CP_WAIT0()  asm volatile("cp.async.wait_group 0;" ::: "memory")

// ---------------- zero the atomic-accumulated buffers ---------------------
__global__ void k_zero() {
    const size_t i = ((size_t)blockIdx.x * 256 + threadIdx.x) * 4;
    float4 z = {0.f, 0.f, 0.f, 0.f};
    *(float4*)(g_h2 + i) = z;
    *(float4*)(g_x2 + i) = z;
}

// ======== generic tf32 GEMM: C = A[M,K] @ B  (CTA 128x256) ================
// (proven; CDST==1 epilogue now stores rna(v) so attention's cp.async B path
//  sees pre-rounded tf32 values)
template <int BLAYOUT, int EPI, int ASRC, int CDST, int TERMS, int NSPLIT>
__global__ void __launch_bounds__(512, 1) k_gemm_tc(
    const float* __restrict__ Ap, int lda, size_t strideA, int a_shift,
    const float* __restrict__ Bp, int ldb, size_t strideB, int b_mask,
    float* __restrict__ Cp, int ldc, size_t strideC,
    const float* __restrict__ bias, int K)
{
    constexpr int OAH = 0;
    constexpr int OAL = 4096;
    constexpr int OBH = (TERMS >= 2) ? 8192 : 4096;

    extern __shared__ float sg[];
    const int tid = threadIdx.x;
    const int lane = tid & 31, wid = tid >> 5;
    const int wm = wid >> 2, wn = wid & 3;
    const int quad = lane >> 2, four = lane & 3;
    const int z = blockIdx.z;
    const int i0 = blockIdx.x * 128;

    const float* Abase = (ASRC == 0) ? Ap : (ASRC == 1) ? g_x1 : g_x2;
    float*       Cbase = (CDST == 0) ? Cp : (CDST == 1) ? g_h
                       : (CDST == 2) ? g_h2 : g_x2;

    int zb = z, ks = 0;
    if (NSPLIT > 1) { zb = z / NSPLIT; ks = z % NSPLIT; }
    const int kb0 = (NSPLIT > 1) ? ks * (K / NSPLIT) : 0;

    const float* A  = Abase + (size_t)((NSPLIT > 1) ? zb : (z >> a_shift)) * strideA;
    const float* Bb = Bp + (size_t)(((NSPLIT > 1) ? zb : z) & b_mask) * strideB;
    float* C = Cbase + (size_t)zb * strideC;

    const int swm = tid >> 7;
    const int skq = (tid >> 5) & 3;
    const int sln = tid & 31;
    const int arow = i0 + swm * 32 + (sln >> 2);
    const int nbas = swm * 64 + (sln >> 2);
    const int kof  = skq * 8 + (sln & 3);
    const int NCH  = (K / NSPLIT) >> 5;

    float av[8], bv[16];
    auto load_chunk = [&](int kbase) {
#pragma unroll
        for (int smi = 0; smi < 2; smi++)
#pragma unroll
            for (int tk = 0; tk < 2; tk++)
#pragma unroll
                for (int tm = 0; tm < 2; tm++)
                    av[smi * 4 + tk * 2 + tm] =
                        A[(size_t)(arow + smi * 16 + tm * 8) * lda + kbase + kof + tk * 4];
#pragma unroll
        for (int sn = 0; sn < 8; sn++)
#pragma unroll
            for (int t = 0; t < 2; t++)
                bv[sn * 2 + t] = (BLAYOUT == 0)
                    ? Bb[(size_t)(kbase + kof + t * 4) * ldb + nbas + sn * 8]
                    : Bb[(size_t)(nbas + sn * 8) * ldb + kbase + kof + t * 4];
    };
    auto store_chunk = [&]() {
        float* ah = sg + OAH + swm * 1024 + skq * 256;
#pragma unroll
        for (int smi = 0; smi < 2; smi++) {
            float4 h4, l4;
            float* hp = &h4.x; float* lp = &l4.x;
#pragma unroll
            for (int q = 0; q < 4; q++) {
                const float v = av[smi * 4 + q];
                const float hi = rna(v);
                hp[q] = hi;
                if constexpr (TERMS >= 2) lp[q] = rna(v - hi);
            }
            *(float4*)(ah + smi * 128 + sln * 4) = h4;
            if constexpr (TERMS >= 2) {
                float* al = sg + OAL + swm * 1024 + skq * 256;
                *(float4*)(al + smi * 128 + sln * 4) = l4;
            }
        }
        float* bh = sg + OBH + swm * 2048 + skq * 512;
#pragma unroll
        for (int sn = 0; sn < 8; sn++) {
            float2 h2;
            h2.x = rna(bv[sn * 2]);
            h2.y = rna(bv[sn * 2 + 1]);
            *(float2*)(bh + sn * 64 + sln * 2) = h2;
        }
    };

    load_chunk(kb0);
    float acc[2][8][4] = {};

    for (int k = 0; k < NCH; k++) {
        __syncthreads();
        store_chunk();
        __syncthreads();
        if (k + 1 < NCH) load_chunk(kb0 + (k + 1) * 32);
        const float* ah = sg + OAH + wm * 1024;
        const float* bh = sg + OBH + wn * 2048;
#pragma unroll
        for (int kq = 0; kq < 4; kq++) {
            float4 a_h[2];
            a_h[0] = *(const float4*)(ah + kq * 256 + lane * 4);
            a_h[1] = *(const float4*)(ah + kq * 256 + 128 + lane * 4);
            if constexpr (TERMS == 2) {
                const float* al = sg + OAL + wm * 1024;
                float4 a_l[2];
                a_l[0] = *(const float4*)(al + kq * 256 + lane * 4);
                a_l[1] = *(const float4*)(al + kq * 256 + 128 + lane * 4);
#pragma unroll
                for (int sn = 0; sn < 8; sn++) {
                    const float2 b_h = *(const float2*)(bh + kq * 512 + sn * 64 + lane * 2);
                    mma4(acc[0][sn], a_h[0], b_h);
                    mma4(acc[1][sn], a_h[1], b_h);
                    mma4(acc[0][sn], a_l[0], b_h);
                    mma4(acc[1][sn], a_l[1], b_h);
                }
            } else {
#pragma unroll
                for (int sn = 0; sn < 8; sn++) {
                    const float2 b_h = *(const float2*)(bh + kq * 512 + sn * 64 + lane * 2);
                    mma4(acc[0][sn], a_h[0], b_h);
                    mma4(acc[1][sn], a_h[1], b_h);
                }
            }
        }
    }

    const bool addb = (EPI >= 1) && (ks == 0);
#pragma unroll
    for (int smi = 0; smi < 2; smi++) {
#pragma unroll
        for (int sn = 0; sn < 8; sn++) {
            const int r0  = i0 + wm * 32 + smi * 16 + quad;
            const int col = wn * 64 + sn * 8 + (four << 1);
            const float* c = acc[smi][sn];
            float2 v0 = {c[0], c[1]}, v1 = {c[2], c[3]};
            if (addb) {
                const float2 bb = *(const float2*)(bias + col);
                v0.x += bb.x; v0.y += bb.y;
                v1.x += bb.x; v1.y += bb.y;
            }
            if (EPI == 2) {
                v0.x = fmaxf(v0.x, 0.f); v0.y = fmaxf(v0.y, 0.f);
                v1.x = fmaxf(v1.x, 0.f); v1.y = fmaxf(v1.y, 0.f);
            }
            if constexpr (CDST == 1) {   // pre-round h for attention tf32 B path
                v0.x = rna(v0.x); v0.y = rna(v0.y);
                v1.x = rna(v1.x); v1.y = rna(v1.y);
            }
            if constexpr (NSPLIT > 1) {
                float* d0 = C + (size_t)r0 * ldc + col;
                float* d1 = C + (size_t)(r0 + 8) * ldc + col;
                atomicAdd(d0,     v0.x); atomicAdd(d0 + 1, v0.y);
                atomicAdd(d1,     v1.x); atomicAdd(d1 + 1, v1.y);
            } else {
                *(float2*)(C + (size_t)r0 * ldc + col)       = v0;
                *(float2*)(C + (size_t)(r0 + 8) * ldc + col) = v1;
            }
        }
    }
}

// ======== fragment-major attention, 64x256 tile, 2 CTAs/SM ================
// 256 threads, 8 warps (2x4). A = p built on the fly (fragment-aligned),
// B = h via cp.async direct to smem. Double-buffered, ONE barrier per chunk.
// MODE 0: multihead -> elu -> x1 concat. MODE 1: single, atomicAdd into x2,
// j-split over blockIdx.z (S partitions).
template <int MODE, int S>
__global__ void __launch_bounds__(256, 2) k_attn_frag(const float* __restrict__ adj) {
    constexpr int CH = NCHUNK / S;
    extern __shared__ float sm[];
    float* s1s = sm + ATT_S1;
    float* rzs = sm + ATT_RZ;

    const int tid = threadIdx.x;
    const int lane = tid & 31, wid = tid >> 5;
    const int wm = wid >> 2, wn = wid & 3;          // 2 x 4 warp grid
    const int quad = lane >> 2, four = lane & 3;
    const int bh = blockIdx.y;
    const int b  = MODE ? bh : (bh >> 3);
    const int i0 = blockIdx.x * 64;
    const int jbase = blockIdx.z * (N / S);

    const float* s1g  = MODE ? g_s1b : g_s1;
    const float* s2g  = MODE ? g_s2b : g_s2;
    const float* rzg  = MODE ? g_rzb : g_rz;
    const float* hsrc = (MODE ? g_h2 : g_h) + (size_t)bh * N * O;
    const float* s2p  = s2g + bh * N;

    if (tid < 64) {
        const int r = bh * N + i0 + tid;
        s1s[tid] = s1g[r]; rzs[tid] = rzg[r];
    }
    __syncthreads();

    // staging ids: 256 threads = swm(2) x skq(4) x sln(32)
    const int swm = tid >> 7;
    const int skq = (tid >> 5) & 3;
    const int sln = tid & 31;
    const int mrow0 = swm * 32 + (sln >> 2);
    const int kof   = skq * 8 + (sln & 3);

    float s1r[4], rzr[4];
#pragma unroll
    for (int smi = 0; smi < 2; smi++)
#pragma unroll
        for (int tm = 0; tm < 2; tm++) {
            const int m = mrow0 + smi * 16 + tm * 8;
            s1r[smi * 2 + tm] = s1s[m];
            rzr[smi * 2 + tm] = rzs[m];
        }
    const float* adjb = adj + (size_t)(b * N + i0 + mrow0) * N;

    const uint32_t bBbase = smem_u32(sm + ATT_B0) + (uint32_t)(skq * 512 + sln * 2) * 4;

    float av[8], s2v0, s2v1;
    auto ldgA = [&](int j0) {
        s2v0 = s2p[j0 + kof];
        s2v1 = s2p[j0 + kof + 4];
#pragma unroll
        for (int smi = 0; smi < 2; smi++)
#pragma unroll
            for (int tk = 0; tk < 2; tk++)
#pragma unroll
                for (int tm = 0; tm < 2; tm++)
                    av[smi * 4 + tk * 2 + tm] =
                        adjb[(size_t)(smi * 16 + tm * 8) * N + j0 + kof + tk * 4];
    };
    auto cpB = [&](int j0, int sbuf) {
        const float* hp = hsrc + (size_t)(j0 + kof) * O + (sln >> 2);
        const uint32_t d0 = bBbase + (uint32_t)(sbuf * 8192) * 4;
#pragma unroll
        for (int w2 = 0; w2 < 2; w2++) {
            const int wnv = swm * 2 + w2;
#pragma unroll
            for (int sn = 0; sn < 8; sn++)
#pragma unroll
                for (int t = 0; t < 2; t++)
                    cp4(d0 + (uint32_t)(wnv * 2048 + sn * 64 + t) * 4,
                        hp + (size_t)t * 4 * O + wnv * 64 + sn * 8);
        }
        CP_COMMIT();
    };
    auto storeA = [&](int sbuf) {
        float* ah = sm + ATT_A0 + sbuf * 2048 + swm * 1024 + skq * 256;
#pragma unroll
        for (int smi = 0; smi < 2; smi++) {
            float4 h4;
            float* hp = &h4.x;
#pragma unroll
            for (int tk = 0; tk < 2; tk++)
#pragma unroll
                for (int tm = 0; tm < 2; tm++) {
                    const int ri = smi * 2 + tm;
                    const float a = av[smi * 4 + tk * 2 + tm];
                    const float s2v = tk ? s2v1 : s2v0;
                    hp[tk * 2 + tm] = (a > 0.f)
                        ? rna(__expf(lrelu(s1r[ri] + s2v)) * rzr[ri]) : 0.f;
                }
            *(float4*)(ah + smi * 128 + sln * 4) = h4;
        }
    };

    // prologue
    ldgA(jbase);
    cpB(jbase, 0);
    float acc[2][8][4] = {};

    for (int k = 0; k < CH; k++) {
        const int s = k & 1;
        storeA(s);                 // writes Abuf[s]; prior readers done at sync(k-1)
        CP_WAIT0();                // B(k) landed
        __syncthreads();           // A(k)+B(k) visible; mma(k-1) readers done
        if (k + 1 < CH) {
            ldgA(jbase + (k + 1) * KC);
            cpB(jbase + (k + 1) * KC, s ^ 1);   // safe: post-sync(k)
        }
        const float* ah  = sm + ATT_A0 + s * 2048 + wm * 1024;
        const float* bhf = sm + ATT_B0 + s * 8192 + wn * 2048;
#pragma unroll
        for (int kq = 0; kq < 4; kq++) {
            float4 a_h[2];
            a_h[0] = *(const float4*)(ah + kq * 256 + lane * 4);
            a_h[1] = *(const float4*)(ah + kq * 256 + 128 + lane * 4);
#pragma unroll
            for (int sn = 0; sn < 8; sn++) {
                const float2 b_h = *(const float2*)(bhf + kq * 512 + sn * 64 + lane * 2);
                mma4(acc[0][sn], a_h[0], b_h);
                mma4(acc[1][sn], a_h[1], b_h);
            }
        }
    }

#pragma unroll
    for (int smi = 0; smi < 2; smi++) {
#pragma unroll
        for (int sn = 0; sn < 8; sn++) {
            const int row0 = i0 + wm * 32 + smi * 16 + quad;
            const int col  = wn * 64 + sn * 8 + (four << 1);
            const float* c = acc[smi][sn];
            if (MODE == 0) {
                float* d0 = g_x1 + ((size_t)b * N + row0) * HO + (bh & 7) * O + col;
                float* d1 = d0 + (size_t)8 * HO;
                float2 v0 = {eluf(c[0]), eluf(c[1])};
                float2 v1 = {eluf(c[2]), eluf(c[3])};
                *(float2*)d0 = v0;
                *(float2*)d1 = v1;
            } else {
                float* d0 = g_x2 + ((size_t)b * N + row0) * O + col;
                float* d1 = d0 + (size_t)8 * O;
                atomicAdd(d0,     c[0]); atomicAdd(d0 + 1, c[1]);
                atomicAdd(d1,     c[2]); atomicAdd(d1 + 1, c[3]);
            }
        }
    }
}

// ---------------- Kernel 2: s1/s2 dots (multi-head) -----------------------
__global__ void k_sdots_multi(const float* __restrict__ ah) {
    const int gt = blockIdx.x * 256 + threadIdx.x;
    const int gw = gt >> 5, lane = gt & 31;
    const int hh = (gw / N) & 7;
    const int b  = gw / (N * H);
    const int n  = gw % N;
    const float4* hr = (const float4*)(g_h + (size_t)gw * O);
    const float4* a1 = (const float4*)(ah + (size_t)hh * 2 * O);
    const float4* a2 = a1 + O / 4;
    float d1 = 0.f, d2 = 0.f;
#pragma unroll
    for (int t = 0; t < 2; t++) {
        const int idx = lane * 2 + t;
        const float4 hv = hr[idx], av = a1[idx], bv = a2[idx];
        d1 += hv.x * av.x + hv.y * av.y + hv.z * av.z + hv.w * av.w;
        d2 += hv.x * bv.x + hv.y * bv.y + hv.z * bv.z + hv.w * bv.w;
    }
#pragma unroll
    for (int s = 16; s; s >>= 1) {
        d1 += __shfl_xor_sync(0xffffffffu, d1, s);
        d2 += __shfl_xor_sync(0xffffffffu, d2, s);
    }
    if (lane == 0) {
        g_s1[gw] = d1;
        g_s2[gw] = d2;
        g_s2t[((size_t)b * N + n) * H + hh] = d2;
    }
}

// ---------------- Kernel 3: softmax Z (no max; e bounded) -----------------
__global__ void k_stats_multi(const float* __restrict__ adj) {
    const int bi = blockIdx.x;
    const int b  = bi >> 11;
    const int i  = bi & (N - 1);
    const int tid = threadIdx.x, lane = tid & 31, wid = tid >> 5;

    float s1v[H];
#pragma unroll
    for (int hh = 0; hh < H; hh++) s1v[hh] = g_s1[(b * H + hh) * N + i];
    float zs[H];
#pragma unroll
    for (int hh = 0; hh < H; hh++) zs[hh] = 0.f;

    const float* arow = adj + (size_t)bi * N;
    for (int j = tid; j < N; j += 256) {
        if (arow[j] > 0.f) {
            const float4* s2p = (const float4*)(g_s2t + (size_t)(b * N + j) * H);
            const float4 sa = s2p[0], sb = s2p[1];
            const float sv[8] = {sa.x, sa.y, sa.z, sa.w, sb.x, sb.y, sb.z, sb.w};
#pragma unroll
            for (int hh = 0; hh < H; hh++)
                zs[hh] += __expf(lrelu(s1v[hh] + sv[hh]));
        }
    }
#pragma unroll
    for (int hh = 0; hh < H; hh++)
        for (int s = 16; s; s >>= 1)
            zs[hh] += __shfl_xor_sync(0xffffffffu, zs[hh], s);
    __shared__ float smz[8][8];
    if (lane == 0) {
#pragma unroll
        for (int hh = 0; hh < H; hh++) smz[wid][hh] = zs[hh];
    }
    __syncthreads();
    if (tid < 8) {
        float zt = 0.f;
#pragma unroll
        for (int w = 0; w < 8; w++) zt += smz[w][tid];
        g_rz[(b * H + tid) * N + i] = 1.f / zt;
    }
}

// ---------------- Kernel 6: single-head s dots ----------------------------
__global__ void k_sdots_single(const float* __restrict__ aout) {
    const int gt = blockIdx.x * 256 + threadIdx.x;
    const int gw = gt >> 5, lane = gt & 31;
    const float4* hr = (const float4*)(g_h2 + (size_t)gw * O);
    const float4* a1 = (const float4*)(aout);
    const float4* a2 = (const float4*)(aout + O);
    float d1 = 0.f, d2 = 0.f;
#pragma unroll
    for (int t = 0; t < 2; t++) {
        const int idx = lane * 2 + t;
        const float4 hv = hr[idx], av = a1[idx], bv = a2[idx];
        d1 += hv.x * av.x + hv.y * av.y + hv.z * av.z + hv.w * av.w;
        d2 += hv.x * bv.x + hv.y * bv.y + hv.z * bv.z + hv.w * bv.w;
    }
#pragma unroll
    for (int s = 16; s; s >>= 1) {
        d1 += __shfl_xor_sync(0xffffffffu, d1, s);
        d2 += __shfl_xor_sync(0xffffffffu, d2, s);
    }
    if (lane == 0) { g_s1b[gw] = d1; g_s2b[gw] = d2; }
}

// ---------------- Kernel 7: single-head softmax Z -------------------------
__global__ void k_stats_single(const float* __restrict__ adj) {
    const int bi = blockIdx.x;
    const int b  = bi >> 11;
    const int tid = threadIdx.x, lane = tid & 31, wid = tid >> 5;
    const float s1v = g_s1b[bi];
    const float* arow = adj + (size_t)bi * N;
    float zs = 0.f;
    for (int j = tid; j < N; j += 256) {
        if (arow[j] > 0.f)
            zs += __expf(lrelu(s1v + g_s2b[b * N + j]));
    }
    for (int s = 16; s; s >>= 1)
        zs += __shfl_xor_sync(0xffffffffu, zs, s);
    __shared__ float smz[8];
    if (lane == 0) smz[wid] = zs;
    __syncthreads();
    if (tid == 0) {
        float zt = 0.f;
#pragma unroll
        for (int w = 0; w < 8; w++) zt += smz[w];
        g_rzb[bi] = 1.f / zt;
    }
}

// ---------------- launch --------------------------------------------------
extern "C" void kernel_launch(void* const* d_in, const int* in_sizes, int n_in,
                              void* d_out, int out_size) {
    const float* x       = (const float*)d_in[0];
    const float* adj     = (const float*)d_in[1];
    const float* W_heads = (const float*)d_in[3];
    const float* a_heads = (const float*)d_in[4];
    const float* W_out   = (const float*)d_in[5];
    const float* a_out   = (const float*)d_in[6];
    const float* W_lin   = (const float*)d_in[7];
    const float* b_lin   = (const float*)d_in[8];
    const float* W_ln    = (const float*)d_in[9];
    const float* b_ln    = (const float*)d_in[10];
    float* out = (float*)d_out;

    cudaFuncSetAttribute(k_attn_frag<0, 1>, cudaFuncAttributeMaxDynamicSharedMemorySize, SMEM_ATTN_BYTES);
    cudaFuncSetAttribute(k_attn_frag<1, 4>, cudaFuncAttributeMaxDynamicSharedMemorySize, SMEM_ATTN_BYTES);
    cudaFuncSetAttribute(k_gemm_tc<0, 0, 0, 1, 2, 1>, cudaFuncAttributeMaxDynamicSharedMemorySize, SMEM_GEMM2_BYTES);
    cudaFuncSetAttribute(k_gemm_tc<0, 0, 1, 2, 1, 4>, cudaFuncAttributeMaxDynamicSharedMemorySize, SMEM_GEMM1_BYTES);
    cudaFuncSetAttribute(k_gemm_tc<1, 1, 1, 3, 1, 4>, cudaFuncAttributeMaxDynamicSharedMemorySize, SMEM_GEMM1_BYTES);
    cudaFuncSetAttribute(k_gemm_tc<1, 2, 2, 0, 1, 1>, cudaFuncAttributeMaxDynamicSharedMemorySize, SMEM_GEMM1_BYTES);

    // zero atomic-accumulation targets (g_h2, g_x2)
    k_zero<<<1024, 256>>>();
    // layer-0 projection: h[bh] = x[b] @ W_heads[h] (2-term split, rna'd out)
    k_gemm_tc<0, 0, 0, 1, 2, 1><<<dim3(16, 1, B * H), 512, SMEM_GEMM2_BYTES>>>(
        x, F, (size_t)N * F, 3,
        W_heads, O, (size_t)F * O, 7,
        nullptr, O, (size_t)N * O,
        nullptr, F);
    k_sdots_multi <<<(B * H * N) / 8, 256>>>(a_heads);
    k_stats_multi <<<B * N, 256>>>(adj);
    // multihead attention: 64-row tiles, 2 CTAs/SM
    k_attn_frag<0, 1><<<dim3(N / 64, B * H, 1), 256, SMEM_ATTN_BYTES>>>(adj);
    // h2 = x1 @ W_out   (single tf32, split-K4)
    k_gemm_tc<0, 0, 1, 2, 1, 4><<<dim3(16, 1, B * 4), 512, SMEM_GEMM1_BYTES>>>(
        nullptr, HO, (size_t)N * HO, 0,
        W_out, O, 0, 0,
        nullptr, O, (size_t)N * O,
        nullptr, HO);
    // x2 = x1 @ W_lin^T + b_lin   (single tf32, split-K4)
    k_gemm_tc<1, 1, 1, 3, 1, 4><<<dim3(16, 1, B * 4), 512, SMEM_GEMM1_BYTES>>>(
        nullptr, HO, (size_t)N * HO, 0,
        W_lin, HO, 0, 0,
        nullptr, O, (size_t)N * O,
        b_lin, HO);
    k_sdots_single<<<(B * N) / 8, 256>>>(a_out);
    k_stats_single<<<B * N, 256>>>(adj);
    // single-head attention, 64-row tiles, j-split x4
    k_attn_frag<1, 4><<<dim3(N / 64, B, 4), 256, SMEM_ATTN_BYTES>>>(adj);
    // out = relu(x2 @ W_ln^T + b_ln)
    k_gemm_tc<1, 2, 2, 0, 1, 1><<<dim3(32, 1, 1), 512, SMEM_GEMM1_BYTES>>>(
        nullptr, O, 0, 0,
        W_ln, O, 0, 0,
        out, O, 0,
        b_ln, O);
}

// round 14
// speedup vs baseline: 1.4113x; 1.4113x over previous
#include <cuda_runtime.h>
#include <cuda_fp16.h>
#include <cstdint>

// Problem constants
namespace {
constexpr int B = 2, N = 2048, F = 768, H = 8, O = 256, HO = H * O;
constexpr float ALPHA = 0.2f;
constexpr int KC = 32;
constexpr int NCHUNK = N / KC;         // 64
constexpr int NCH32 = N / 32;          // chunks per row block
// attn smem (32-bit words): A 2x2048, B 2x4096, s1 128, rz 128
constexpr int AT_A0 = 0;
constexpr int AT_B0 = 4096;
constexpr int AT_S1 = 12288;
constexpr int AT_RZ = 12416;
constexpr int SMEM_ATTN_BYTES  = 12544 * 4;          // 50176
constexpr int SMEM_GEMM2_BYTES = 16384 * 4;          // 65536 (hi/lo A, hi B)
constexpr int SMEM_GEMM1_BYTES = 12288 * 4;          // 49152 (hi only)
}

// ---------------- scratch (static device globals; no allocation) ----------
// ONLY referenced from device code (host-passing them hands over the host
// shadow symbol -> ATS silent corruption; round-6/8 bug).
__device__ float g_h  [(size_t)B * H * N * O];
__device__ float g_s1 [B * H * N];
__device__ float g_s2 [B * H * N];
__device__ float g_s2t[B * N * H];
__device__ float g_rz [B * H * N];
__device__ float g_x1 [(size_t)B * N * HO];
__device__ float g_h2 [(size_t)B * N * O];
__device__ float g_x2 [(size_t)B * N * O];
__device__ float g_s1b[B * N];
__device__ float g_s2b[B * N];
__device__ float g_rzb[B * N];
// fp16 fragment-packed h: [Z][chunk][4096 words]
__device__ uint32_t g_hpk [(size_t)B * H * NCH32 * 4096];
__device__ uint32_t g_h2pk[(size_t)B * NCH32 * 4096];

__device__ __forceinline__ float lrelu(float v) { return v > 0.f ? v : ALPHA * v; }
__device__ __forceinline__ float eluf(float v)  { return v > 0.f ? v : __expf(v) - 1.f; }

__device__ __forceinline__ float rna(float v) {
    uint32_t u; asm("cvt.rna.tf32.f32 %0, %1;" : "=r"(u) : "f"(v));
    return __uint_as_float(u);
}
__device__ __forceinline__ uint32_t f2h2(float lo, float hi) {
    __half2 h = __floats2half2_rn(lo, hi);   // lo -> .x (low 16 bits)
    return *(uint32_t*)&h;
}

// tf32 m16n8k8 (dense gemms)
__device__ __forceinline__ void mma4(float* c, const float4& a, const float2& b) {
    asm volatile(
        "mma.sync.aligned.m16n8k8.row.col.f32.tf32.tf32.f32 "
        "{%0,%1,%2,%3}, {%4,%5,%6,%7}, {%8,%9}, {%0,%1,%2,%3};"
        : "+f"(c[0]), "+f"(c[1]), "+f"(c[2]), "+f"(c[3])
        : "r"(__float_as_uint(a.x)), "r"(__float_as_uint(a.y)),
          "r"(__float_as_uint(a.z)), "r"(__float_as_uint(a.w)),
          "r"(__float_as_uint(b.x)), "r"(__float_as_uint(b.y)));
}
// fp16 m16n8k16 (attention)
__device__ __forceinline__ void mma_f16(float* c, const uint32_t* a,
                                        uint32_t b0, uint32_t b1) {
    asm volatile(
        "mma.sync.aligned.m16n8k16.row.col.f32.f16.f16.f32 "
        "{%0,%1,%2,%3}, {%4,%5,%6,%7}, {%8,%9}, {%0,%1,%2,%3};"
        : "+f"(c[0]), "+f"(c[1]), "+f"(c[2]), "+f"(c[3])
        : "r"(a[0]), "r"(a[1]), "r"(a[2]), "r"(a[3]), "r"(b0), "r"(b1));
}

// ---------------- zero the atomic-accumulated buffers ---------------------
__global__ void k_zero() {
    const size_t i = ((size_t)blockIdx.x * 256 + threadIdx.x) * 4;
    float4 z = {0.f, 0.f, 0.f, 0.f};
    *(float4*)(g_h2 + i) = z;
    *(float4*)(g_x2 + i) = z;
}

// ---------------- pack h into m16n8k16 B-fragment words -------------------
// word index within a 32x256 chunk: ((wn*2+kq)*8+sn)*64 + lane*2 + r
// where lane = quad*4+four; b0(r=0)=(k=kq*16+2f, k+1), b1(r=1)=(+8); col =
// wn*64+sn*8+quad.
template <int MODE>
__global__ void k_pack() {
    __shared__ float t[32][264];
    const int z = blockIdx.y;
    const int ch = blockIdx.x;
    const int tid = threadIdx.x;
    const float* src = (MODE ? g_h2 : g_h) + ((size_t)z * N + ch * 32) * O;
    uint32_t* dst = (MODE ? g_h2pk : g_hpk) + ((size_t)z * NCH32 + ch) * 4096;
#pragma unroll
    for (int it = 0; it < 8; it++) {
        const int idx = it * 1024 + tid * 4;
        const int r = idx >> 8, c = idx & 255;
        *(float4*)&t[r][c] = *(const float4*)(src + (size_t)r * O + c);
    }
    __syncthreads();
#pragma unroll
    for (int it = 0; it < 16; it++) {
        const int w = tid * 16 + it;
        const int g = w >> 6;                 // (wn*2+kq)*8+sn
        const int sn = g & 7, wnkq = g >> 3;
        const int kq = wnkq & 1, wn = wnkq >> 1;
        const int rem = w & 63;
        const int r = rem & 1, lf = rem >> 1;
        const int quad = lf >> 2, four = lf & 3;
        const int k = kq * 16 + r * 8 + four * 2;
        const int c = wn * 64 + sn * 8 + quad;
        dst[w] = f2h2(t[k][c], t[k + 1][c]);
    }
}

// ======== generic tf32 GEMM: C = A[M,K] @ B  (CTA 128x256) ================
// (verbatim round 11 — proven)
template <int BLAYOUT, int EPI, int ASRC, int CDST, int TERMS, int NSPLIT>
__global__ void __launch_bounds__(512, 1) k_gemm_tc(
    const float* __restrict__ Ap, int lda, size_t strideA, int a_shift,
    const float* __restrict__ Bp, int ldb, size_t strideB, int b_mask,
    float* __restrict__ Cp, int ldc, size_t strideC,
    const float* __restrict__ bias, int K)
{
    constexpr int OAH = 0;
    constexpr int OAL = 4096;
    constexpr int OBH = (TERMS >= 2) ? 8192 : 4096;

    extern __shared__ float sg[];
    const int tid = threadIdx.x;
    const int lane = tid & 31, wid = tid >> 5;
    const int wm = wid >> 2, wn = wid & 3;
    const int quad = lane >> 2, four = lane & 3;
    const int z = blockIdx.z;
    const int i0 = blockIdx.x * 128;

    const float* Abase = (ASRC == 0) ? Ap : (ASRC == 1) ? g_x1 : g_x2;
    float*       Cbase = (CDST == 0) ? Cp : (CDST == 1) ? g_h
                       : (CDST == 2) ? g_h2 : g_x2;

    int zb = z, ks = 0;
    if (NSPLIT > 1) { zb = z / NSPLIT; ks = z % NSPLIT; }
    const int kb0 = (NSPLIT > 1) ? ks * (K / NSPLIT) : 0;

    const float* A  = Abase + (size_t)((NSPLIT > 1) ? zb : (z >> a_shift)) * strideA;
    const float* Bb = Bp + (size_t)(((NSPLIT > 1) ? zb : z) & b_mask) * strideB;
    float* C = Cbase + (size_t)zb * strideC;

    const int swm = tid >> 7;
    const int skq = (tid >> 5) & 3;
    const int sln = tid & 31;
    const int arow = i0 + swm * 32 + (sln >> 2);
    const int nbas = swm * 64 + (sln >> 2);
    const int kof  = skq * 8 + (sln & 3);
    const int NCH  = (K / NSPLIT) >> 5;

    float av[8], bv[16];
    auto load_chunk = [&](int kbase) {
#pragma unroll
        for (int smi = 0; smi < 2; smi++)
#pragma unroll
            for (int tk = 0; tk < 2; tk++)
#pragma unroll
                for (int tm = 0; tm < 2; tm++)
                    av[smi * 4 + tk * 2 + tm] =
                        A[(size_t)(arow + smi * 16 + tm * 8) * lda + kbase + kof + tk * 4];
#pragma unroll
        for (int sn = 0; sn < 8; sn++)
#pragma unroll
            for (int t = 0; t < 2; t++)
                bv[sn * 2 + t] = (BLAYOUT == 0)
                    ? Bb[(size_t)(kbase + kof + t * 4) * ldb + nbas + sn * 8]
                    : Bb[(size_t)(nbas + sn * 8) * ldb + kbase + kof + t * 4];
    };
    auto store_chunk = [&]() {
        float* ah = sg + OAH + swm * 1024 + skq * 256;
#pragma unroll
        for (int smi = 0; smi < 2; smi++) {
            float4 h4, l4;
            float* hp = &h4.x; float* lp = &l4.x;
#pragma unroll
            for (int q = 0; q < 4; q++) {
                const float v = av[smi * 4 + q];
                const float hi = rna(v);
                hp[q] = hi;
                if constexpr (TERMS >= 2) lp[q] = rna(v - hi);
            }
            *(float4*)(ah + smi * 128 + sln * 4) = h4;
            if constexpr (TERMS >= 2) {
                float* al = sg + OAL + swm * 1024 + skq * 256;
                *(float4*)(al + smi * 128 + sln * 4) = l4;
            }
        }
        float* bh = sg + OBH + swm * 2048 + skq * 512;
#pragma unroll
        for (int sn = 0; sn < 8; sn++) {
            float2 h2;
            h2.x = rna(bv[sn * 2]);
            h2.y = rna(bv[sn * 2 + 1]);
            *(float2*)(bh + sn * 64 + sln * 2) = h2;
        }
    };

    load_chunk(kb0);
    float acc[2][8][4] = {};

    for (int k = 0; k < NCH; k++) {
        __syncthreads();
        store_chunk();
        __syncthreads();
        if (k + 1 < NCH) load_chunk(kb0 + (k + 1) * 32);
        const float* ah = sg + OAH + wm * 1024;
        const float* bh = sg + OBH + wn * 2048;
#pragma unroll
        for (int kq = 0; kq < 4; kq++) {
            float4 a_h[2];
            a_h[0] = *(const float4*)(ah + kq * 256 + lane * 4);
            a_h[1] = *(const float4*)(ah + kq * 256 + 128 + lane * 4);
            if constexpr (TERMS == 2) {
                const float* al = sg + OAL + wm * 1024;
                float4 a_l[2];
                a_l[0] = *(const float4*)(al + kq * 256 + lane * 4);
                a_l[1] = *(const float4*)(al + kq * 256 + 128 + lane * 4);
#pragma unroll
                for (int sn = 0; sn < 8; sn++) {
                    const float2 b_h = *(const float2*)(bh + kq * 512 + sn * 64 + lane * 2);
                    mma4(acc[0][sn], a_h[0], b_h);
                    mma4(acc[1][sn], a_h[1], b_h);
                    mma4(acc[0][sn], a_l[0], b_h);
                    mma4(acc[1][sn], a_l[1], b_h);
                }
            } else {
#pragma unroll
                for (int sn = 0; sn < 8; sn++) {
                    const float2 b_h = *(const float2*)(bh + kq * 512 + sn * 64 + lane * 2);
                    mma4(acc[0][sn], a_h[0], b_h);
                    mma4(acc[1][sn], a_h[1], b_h);
                }
            }
        }
    }

    const bool addb = (EPI >= 1) && (ks == 0);
#pragma unroll
    for (int smi = 0; smi < 2; smi++) {
#pragma unroll
        for (int sn = 0; sn < 8; sn++) {
            const int r0  = i0 + wm * 32 + smi * 16 + quad;
            const int col = wn * 64 + sn * 8 + (four << 1);
            const float* c = acc[smi][sn];
            float2 v0 = {c[0], c[1]}, v1 = {c[2], c[3]};
            if (addb) {
                const float2 bb = *(const float2*)(bias + col);
                v0.x += bb.x; v0.y += bb.y;
                v1.x += bb.x; v1.y += bb.y;
            }
            if (EPI == 2) {
                v0.x = fmaxf(v0.x, 0.f); v0.y = fmaxf(v0.y, 0.f);
                v1.x = fmaxf(v1.x, 0.f); v1.y = fmaxf(v1.y, 0.f);
            }
            if constexpr (NSPLIT > 1) {
                float* d0 = C + (size_t)r0 * ldc + col;
                float* d1 = C + (size_t)(r0 + 8) * ldc + col;
                atomicAdd(d0,     v0.x); atomicAdd(d0 + 1, v0.y);
                atomicAdd(d1,     v1.x); atomicAdd(d1 + 1, v1.y);
            } else {
                *(float2*)(C + (size_t)r0 * ldc + col)       = v0;
                *(float2*)(C + (size_t)(r0 + 8) * ldc + col) = v1;
            }
        }
    }
}

// ======== fp16 m16n8k16 attention: D = p @ h  (CTA 128x256) ===============
// A (p) built on the fly directly as fragment half2 words; B (h) copied from
// pre-packed g_hpk. Round-11 schedule: double buffer, ONE barrier per chunk.
// MODE 0: multihead -> elu -> x1 concat. MODE 1: single, atomicAdd into x2,
// j-split over blockIdx.z (S partitions).
template <int MODE, int S>
__global__ void __launch_bounds__(512, 1) k_attn_f16(const float* __restrict__ adj) {
    constexpr int CH = NCHUNK / S;
    extern __shared__ uint32_t smw[];
    float* s1s = (float*)(smw + AT_S1);
    float* rzs = (float*)(smw + AT_RZ);

    const int tid = threadIdx.x;
    const int lane = tid & 31, wid = tid >> 5;
    const int wm = wid >> 2, wn = wid & 3;
    const int quad = lane >> 2, four = lane & 3;
    const int bh = blockIdx.y;
    const int b  = MODE ? bh : (bh >> 3);
    const int i0 = blockIdx.x * 128;
    const int jbase = blockIdx.z * (N / S);
    const int ch0 = jbase / 32;

    const float* s1g = MODE ? g_s1b : g_s1;
    const float* s2g = MODE ? g_s2b : g_s2;
    const float* rzg = MODE ? g_rzb : g_rz;
    const uint32_t* hpk = (MODE ? g_h2pk : g_hpk) + (size_t)bh * NCH32 * 4096;
    const float* s2p = s2g + bh * N;

    if (tid < 128) {
        const int r = bh * N + i0 + tid;
        s1s[tid] = s1g[r]; rzs[tid] = rzg[r];
    }
    __syncthreads();

    // A staging ids: 512 = swm(4) x skq(2) x ssmi(2) x sln(32)
    const int swm  = tid >> 7;
    const int skq  = (tid >> 6) & 1;
    const int ssmi = (tid >> 5) & 1;
    const int sln  = tid & 31;
    const int sq = sln >> 2, sf = sln & 3;
    const int R0 = i0 + swm * 32 + ssmi * 16 + sq;     // and R0+8
    const int c0 = skq * 16 + sf * 2;                  // cols c0,c0+1,c0+8,c0+9
    const float s1a = s1s[R0 - i0],     rza = rzs[R0 - i0];
    const float s1b = s1s[R0 - i0 + 8], rzb = rzs[R0 - i0 + 8];
    const float* adjA = adj + (size_t)(b * N + R0) * N;
    const float* adjB = adjA + (size_t)8 * N;

    float2 aA0, aA8, aB0, aB8, s2lo, s2hi;
    uint4 hb0, hb1;
    auto loadA = [&](int j0) {
        aA0 = *(const float2*)(adjA + j0 + c0);
        aA8 = *(const float2*)(adjA + j0 + c0 + 8);
        aB0 = *(const float2*)(adjB + j0 + c0);
        aB8 = *(const float2*)(adjB + j0 + c0 + 8);
        s2lo = *(const float2*)(s2p + j0 + c0);
        s2hi = *(const float2*)(s2p + j0 + c0 + 8);
    };
    auto loadB = [&](int ch) {
        const uint4* src = (const uint4*)(hpk + (size_t)ch * 4096) + tid * 2;
        hb0 = src[0];
        hb1 = src[1];
    };
    auto pval = [&](float a, float s1v, float rz, float s2v) -> float {
        return (a > 0.f) ? __expf(lrelu(s1v + s2v)) * rz : 0.f;
    };
    auto store_chunk = [&](int s) {
        // A fragment words
        const float p00 = pval(aA0.x, s1a, rza, s2lo.x);
        const float p01 = pval(aA0.y, s1a, rza, s2lo.y);
        const float p02 = pval(aA8.x, s1a, rza, s2hi.x);
        const float p03 = pval(aA8.y, s1a, rza, s2hi.y);
        const float p10 = pval(aB0.x, s1b, rzb, s2lo.x);
        const float p11 = pval(aB0.y, s1b, rzb, s2lo.y);
        const float p12 = pval(aB8.x, s1b, rzb, s2hi.x);
        const float p13 = pval(aB8.y, s1b, rzb, s2hi.y);
        uint4 w;
        w.x = f2h2(p00, p01);   // a0: (R0, c0), (R0, c0+1)
        w.y = f2h2(p10, p11);   // a1: (R0+8, ...)
        w.z = f2h2(p02, p03);   // a2: (R0, c0+8), (R0, c0+9)
        w.w = f2h2(p12, p13);   // a3
        *(uint4*)(smw + AT_A0 + s * 2048 + (((swm * 2 + skq) * 2 + ssmi) * 128 + sln * 4)) = w;
        // B copy
        uint4* bd = (uint4*)(smw + AT_B0 + s * 4096) + tid * 2;
        bd[0] = hb0;
        bd[1] = hb1;
    };

    loadA(jbase);
    loadB(ch0);
    store_chunk(0);
    __syncthreads();

    float acc[2][8][4] = {};

    for (int k = 0; k < CH; k++) {
        const int s = k & 1;
        if (k + 1 < CH) {
            loadA(jbase + (k + 1) * KC);
            loadB(ch0 + k + 1);
        }
        // mma on buffer s
        const uint32_t* Ab = smw + AT_A0 + s * 2048;
        const uint32_t* Bb = smw + AT_B0 + s * 4096;
#pragma unroll
        for (int kq = 0; kq < 2; kq++) {
            uint4 aw[2];
            aw[0] = *(const uint4*)(Ab + ((wm * 2 + kq) * 2 + 0) * 128 + lane * 4);
            aw[1] = *(const uint4*)(Ab + ((wm * 2 + kq) * 2 + 1) * 128 + lane * 4);
#pragma unroll
            for (int sn = 0; sn < 8; sn++) {
                const uint2 bw = *(const uint2*)(Bb + ((wn * 2 + kq) * 8 + sn) * 64 + lane * 2);
                mma_f16(acc[0][sn], (const uint32_t*)&aw[0], bw.x, bw.y);
                mma_f16(acc[1][sn], (const uint32_t*)&aw[1], bw.x, bw.y);
            }
        }
        if (k + 1 < CH) store_chunk(s ^ 1);
        __syncthreads();
    }

#pragma unroll
    for (int smi = 0; smi < 2; smi++) {
#pragma unroll
        for (int sn = 0; sn < 8; sn++) {
            const int row0 = i0 + wm * 32 + smi * 16 + quad;
            const int col  = wn * 64 + sn * 8 + (four << 1);
            const float* c = acc[smi][sn];
            if (MODE == 0) {
                float* d0 = g_x1 + ((size_t)b * N + row0) * HO + (bh & 7) * O + col;
                float* d1 = d0 + (size_t)8 * HO;
                float2 v0 = {eluf(c[0]), eluf(c[1])};
                float2 v1 = {eluf(c[2]), eluf(c[3])};
                *(float2*)d0 = v0;
                *(float2*)d1 = v1;
            } else {
                float* d0 = g_x2 + ((size_t)b * N + row0) * O + col;
                float* d1 = d0 + (size_t)8 * O;
                atomicAdd(d0,     c[0]); atomicAdd(d0 + 1, c[1]);
                atomicAdd(d1,     c[2]); atomicAdd(d1 + 1, c[3]);
            }
        }
    }
}

// ---------------- Kernel 2: s1/s2 dots (multi-head) -----------------------
__global__ void k_sdots_multi(const float* __restrict__ ah) {
    const int gt = blockIdx.x * 256 + threadIdx.x;
    const int gw = gt >> 5, lane = gt & 31;
    const int hh = (gw / N) & 7;
    const int b  = gw / (N * H);
    const int n  = gw % N;
    const float4* hr = (const float4*)(g_h + (size_t)gw * O);
    const float4* a1 = (const float4*)(ah + (size_t)hh * 2 * O);
    const float4* a2 = a1 + O / 4;
    float d1 = 0.f, d2 = 0.f;
#pragma unroll
    for (int t = 0; t < 2; t++) {
        const int idx = lane * 2 + t;
        const float4 hv = hr[idx], av = a1[idx], bv = a2[idx];
        d1 += hv.x * av.x + hv.y * av.y + hv.z * av.z + hv.w * av.w;
        d2 += hv.x * bv.x + hv.y * bv.y + hv.z * bv.z + hv.w * bv.w;
    }
#pragma unroll
    for (int s = 16; s; s >>= 1) {
        d1 += __shfl_xor_sync(0xffffffffu, d1, s);
        d2 += __shfl_xor_sync(0xffffffffu, d2, s);
    }
    if (lane == 0) {
        g_s1[gw] = d1;
        g_s2[gw] = d2;
        g_s2t[((size_t)b * N + n) * H + hh] = d2;
    }
}

// ---------------- Kernel 3: softmax Z (no max; e bounded) -----------------
__global__ void k_stats_multi(const float* __restrict__ adj) {
    const int bi = blockIdx.x;
    const int b  = bi >> 11;
    const int i  = bi & (N - 1);
    const int tid = threadIdx.x, lane = tid & 31, wid = tid >> 5;

    float s1v[H];
#pragma unroll
    for (int hh = 0; hh < H; hh++) s1v[hh] = g_s1[(b * H + hh) * N + i];
    float zs[H];
#pragma unroll
    for (int hh = 0; hh < H; hh++) zs[hh] = 0.f;

    const float* arow = adj + (size_t)bi * N;
    for (int j = tid; j < N; j += 256) {
        if (arow[j] > 0.f) {
            const float4* s2p = (const float4*)(g_s2t + (size_t)(b * N + j) * H);
            const float4 sa = s2p[0], sb = s2p[1];
            const float sv[8] = {sa.x, sa.y, sa.z, sa.w, sb.x, sb.y, sb.z, sb.w};
#pragma unroll
            for (int hh = 0; hh < H; hh++)
                zs[hh] += __expf(lrelu(s1v[hh] + sv[hh]));
        }
    }
#pragma unroll
    for (int hh = 0; hh < H; hh++)
        for (int s = 16; s; s >>= 1)
            zs[hh] += __shfl_xor_sync(0xffffffffu, zs[hh], s);
    __shared__ float smz[8][8];
    if (lane == 0) {
#pragma unroll
        for (int hh = 0; hh < H; hh++) smz[wid][hh] = zs[hh];
    }
    __syncthreads();
    if (tid < 8) {
        float zt = 0.f;
#pragma unroll
        for (int w = 0; w < 8; w++) zt += smz[w][tid];
        g_rz[(b * H + tid) * N + i] = 1.f / zt;
    }
}

// ---------------- Kernel 6: single-head s dots ----------------------------
__global__ void k_sdots_single(const float* __restrict__ aout) {
    const int gt = blockIdx.x * 256 + threadIdx.x;
    const int gw = gt >> 5, lane = gt & 31;
    const float4* hr = (const float4*)(g_h2 + (size_t)gw * O);
    const float4* a1 = (const float4*)(aout);
    const float4* a2 = (const float4*)(aout + O);
    float d1 = 0.f, d2 = 0.f;
#pragma unroll
    for (int t = 0; t < 2; t++) {
        const int idx = lane * 2 + t;
        const float4 hv = hr[idx], av = a1[idx], bv = a2[idx];
        d1 += hv.x * av.x + hv.y * av.y + hv.z * av.z + hv.w * av.w;
        d2 += hv.x * bv.x + hv.y * bv.y + hv.z * bv.z + hv.w * bv.w;
    }
#pragma unroll
    for (int s = 16; s; s >>= 1) {
        d1 += __shfl_xor_sync(0xffffffffu, d1, s);
        d2 += __shfl_xor_sync(0xffffffffu, d2, s);
    }
    if (lane == 0) { g_s1b[gw] = d1; g_s2b[gw] = d2; }
}

// ---------------- Kernel 7: single-head softmax Z -------------------------
__global__ void k_stats_single(const float* __restrict__ adj) {
    const int bi = blockIdx.x;
    const int b  = bi >> 11;
    const int tid = threadIdx.x, lane = tid & 31, wid = tid >> 5;
    const float s1v = g_s1b[bi];
    const float* arow = adj + (size_t)bi * N;
    float zs = 0.f;
    for (int j = tid; j < N; j += 256) {
        if (arow[j] > 0.f)
            zs += __expf(lrelu(s1v + g_s2b[b * N + j]));
    }
    for (int s = 16; s; s >>= 1)
        zs += __shfl_xor_sync(0xffffffffu, zs, s);
    __shared__ float smz[8];
    if (lane == 0) smz[wid] = zs;
    __syncthreads();
    if (tid == 0) {
        float zt = 0.f;
#pragma unroll
        for (int w = 0; w < 8; w++) zt += smz[w];
        g_rzb[bi] = 1.f / zt;
    }
}

// ---------------- launch --------------------------------------------------
extern "C" void kernel_launch(void* const* d_in, const int* in_sizes, int n_in,
                              void* d_out, int out_size) {
    const float* x       = (const float*)d_in[0];
    const float* adj     = (const float*)d_in[1];
    const float* W_heads = (const float*)d_in[3];
    const float* a_heads = (const float*)d_in[4];
    const float* W_out   = (const float*)d_in[5];
    const float* a_out   = (const float*)d_in[6];
    const float* W_lin   = (const float*)d_in[7];
    const float* b_lin   = (const float*)d_in[8];
    const float* W_ln    = (const float*)d_in[9];
    const float* b_ln    = (const float*)d_in[10];
    float* out = (float*)d_out;

    cudaFuncSetAttribute(k_attn_f16<0, 1>, cudaFuncAttributeMaxDynamicSharedMemorySize, SMEM_ATTN_BYTES);
    cudaFuncSetAttribute(k_attn_f16<1, 4>, cudaFuncAttributeMaxDynamicSharedMemorySize, SMEM_ATTN_BYTES);
    cudaFuncSetAttribute(k_gemm_tc<0, 0, 0, 1, 2, 1>, cudaFuncAttributeMaxDynamicSharedMemorySize, SMEM_GEMM2_BYTES);
    cudaFuncSetAttribute(k_gemm_tc<0, 0, 1, 2, 1, 4>, cudaFuncAttributeMaxDynamicSharedMemorySize, SMEM_GEMM1_BYTES);
    cudaFuncSetAttribute(k_gemm_tc<1, 1, 1, 3, 1, 4>, cudaFuncAttributeMaxDynamicSharedMemorySize, SMEM_GEMM1_BYTES);
    cudaFuncSetAttribute(k_gemm_tc<1, 2, 2, 0, 1, 1>, cudaFuncAttributeMaxDynamicSharedMemorySize, SMEM_GEMM1_BYTES);

    // zero atomic-accumulation targets (g_h2, g_x2)
    k_zero<<<1024, 256>>>();
    // layer-0 projection: h[bh] = x[b] @ W_heads[h] (2-term tf32 split)
    k_gemm_tc<0, 0, 0, 1, 2, 1><<<dim3(16, 1, B * H), 512, SMEM_GEMM2_BYTES>>>(
        x, F, (size_t)N * F, 3,
        W_heads, O, (size_t)F * O, 7,
        nullptr, O, (size_t)N * O,
        nullptr, F);
    k_sdots_multi <<<(B * H * N) / 8, 256>>>(a_heads);
    k_pack<0>     <<<dim3(NCH32, B * H), 256>>>();
    k_stats_multi <<<B * N, 256>>>(adj);
    // multihead attention: fp16 m16n8k16
    k_attn_f16<0, 1><<<dim3(N / 128, B * H, 1), 512, SMEM_ATTN_BYTES>>>(adj);
    // h2 = x1 @ W_out   (single tf32, split-K4)
    k_gemm_tc<0, 0, 1, 2, 1, 4><<<dim3(16, 1, B * 4), 512, SMEM_GEMM1_BYTES>>>(
        nullptr, HO, (size_t)N * HO, 0,
        W_out, O, 0, 0,
        nullptr, O, (size_t)N * O,
        nullptr, HO);
    // x2 = x1 @ W_lin^T + b_lin   (single tf32, split-K4)
    k_gemm_tc<1, 1, 1, 3, 1, 4><<<dim3(16, 1, B * 4), 512, SMEM_GEMM1_BYTES>>>(
        nullptr, HO, (size_t)N * HO, 0,
        W_lin, HO, 0, 0,
        nullptr, O, (size_t)N * O,
        b_lin, HO);
    k_sdots_single<<<(B * N) / 8, 256>>>(a_out);
    k_pack<1>     <<<dim3(NCH32, B), 256>>>();
    k_stats_single<<<B * N, 256>>>(adj);
    // single-head attention, j-split x4
    k_attn_f16<1, 4><<<dim3(N / 128, B, 4), 512, SMEM_ATTN_BYTES>>>(adj);
    // out = relu(x2 @ W_ln^T + b_ln)
    k_gemm_tc<1, 2, 2, 0, 1, 1><<<dim3(32, 1, 1), 512, SMEM_GEMM1_BYTES>>>(
        nullptr, O, 0, 0,
        W_ln, O, 0, 0,
        out, O, 0,
        b_ln, O);
}

// round 17
// speedup vs baseline: 1.7276x; 1.2242x over previous
#include <cuda_runtime.h>
#include <cuda_fp16.h>
#include <cstdint>

// Problem constants
namespace {
constexpr int B = 2, N = 2048, F = 768, H = 8, O = 256, HO = H * O;
constexpr float ALPHA = 0.2f;
constexpr int KC = 32;
constexpr int NCHUNK = N / KC;         // 64
constexpr int NCH32 = N / 32;
// attn smem (32-bit words): A 2x2048, B 2x4096, s1 128, rz 128
constexpr int AT_A0 = 0;
constexpr int AT_B0 = 4096;
constexpr int AT_S1 = 12288;
constexpr int AT_RZ = 12416;
constexpr int SMEM_ATTN_BYTES = 12544 * 4;           // 50176
// fp16 gemm smem (words): AH 2x2048, (AL 2x2048), B 2x4096
constexpr int SMEM_G2_BYTES = 16384 * 4;             // 65536 (TERMS 2)
constexpr int SMEM_G1_BYTES = 12288 * 4;             // 49152 (TERMS 1)
// packed-weight word offsets in g_wpk
constexpr size_t OFF_WH   = 0;                        // 8 z x 24 ch
constexpr size_t OFF_WOUT = OFF_WH   + (size_t)8 * 24 * 4096;
constexpr size_t OFF_WLIN = OFF_WOUT + (size_t)64 * 4096;
constexpr size_t OFF_WLN  = OFF_WLIN + (size_t)64 * 4096;
}

// ---------------- scratch (static device globals; no allocation) ----------
// ONLY referenced from device code (host-passing them hands over the host
// shadow symbol -> ATS silent corruption; round-6/8 bug).
__device__ float g_h  [(size_t)B * H * N * O];
__device__ float g_s1 [B * H * N];
__device__ float g_s2 [B * H * N];
__device__ float g_s2t[B * N * H];
__device__ float g_rz [B * H * N];
__device__ float g_x1 [(size_t)B * N * HO];
__device__ float g_h2 [(size_t)B * N * O];
__device__ float g_x2 [(size_t)B * N * O];
__device__ float g_s1b[B * N];
__device__ float g_s2b[B * N];
__device__ float g_rzb[B * N];
__device__ uint32_t g_hpk [(size_t)B * H * NCH32 * 4096];
__device__ uint32_t g_h2pk[(size_t)B * NCH32 * 4096];
__device__ uint32_t g_wpk [OFF_WLN + (size_t)8 * 4096];   // packed weights

__device__ __forceinline__ float lrelu(float v) { return v > 0.f ? v : ALPHA * v; }
__device__ __forceinline__ float eluf(float v)  { return v > 0.f ? v : __expf(v) - 1.f; }

__device__ __forceinline__ uint32_t f2h2(float lo, float hi) {
    __half2 h = __floats2half2_rn(lo, hi);
    return *(uint32_t*)&h;
}
// split pair into hi word + residual-lo word
__device__ __forceinline__ void split2(float a, float b, uint32_t& hi, uint32_t& lo) {
    const __half ha = __float2half_rn(a), hb = __float2half_rn(b);
    __half2 hh; hh.x = ha; hh.y = hb;
    hi = *(uint32_t*)&hh;
    lo = f2h2(a - __half2float(ha), b - __half2float(hb));
}

__device__ __forceinline__ void mma_f16(float* c, const uint32_t* a,
                                        uint32_t b0, uint32_t b1) {
    asm volatile(
        "mma.sync.aligned.m16n8k16.row.col.f32.f16.f16.f32 "
        "{%0,%1,%2,%3}, {%4,%5,%6,%7}, {%8,%9}, {%0,%1,%2,%3};"
        : "+f"(c[0]), "+f"(c[1]), "+f"(c[2]), "+f"(c[3])
        : "r"(a[0]), "r"(a[1]), "r"(a[2]), "r"(a[3]), "r"(b0), "r"(b1));
}

// ---------------- zero the atomic-accumulated buffers ---------------------
__global__ void k_zero() {
    const size_t i = ((size_t)blockIdx.x * 256 + threadIdx.x) * 4;
    float4 z = {0.f, 0.f, 0.f, 0.f};
    *(float4*)(g_h2 + i) = z;
    *(float4*)(g_x2 + i) = z;
}

// ---------------- pack h / h2 into B-fragment words (proven R14) ----------
template <int MODE>
__global__ void k_pack() {
    __shared__ float t[32][264];
    const int z = blockIdx.y;
    const int ch = blockIdx.x;
    const int tid = threadIdx.x;
    const float* src = (MODE ? g_h2 : g_h) + ((size_t)z * N + ch * 32) * O;
    uint32_t* dst = (MODE ? g_h2pk : g_hpk) + ((size_t)z * NCH32 + ch) * 4096;
#pragma unroll
    for (int it = 0; it < 8; it++) {
        const int idx = it * 1024 + tid * 4;
        const int r = idx >> 8, c = idx & 255;
        *(float4*)&t[r][c] = *(const float4*)(src + (size_t)r * O + c);
    }
    __syncthreads();
#pragma unroll
    for (int it = 0; it < 16; it++) {
        const int w = tid * 16 + it;
        const int g = w >> 6;
        const int sn = g & 7, wnkq = g >> 3;
        const int kq = wnkq & 1, wn = wnkq >> 1;
        const int rem = w & 63;
        const int r = rem & 1, lf = rem >> 1;
        const int quad = lf >> 2, four = lf & 3;
        const int k = kq * 16 + r * 8 + four * 2;
        const int c = wn * 64 + sn * 8 + quad;
        dst[w] = f2h2(t[k][c], t[k + 1][c]);
    }
}

// ---------------- pack weights into B-fragment words ----------------------
// BLAYOUT 0: src[k*ldw + col]; BLAYOUT 1: src[col*ldw + k]. N-dim is 256.
__global__ void k_packB(const float* __restrict__ src, size_t srcZ, int ldw,
                        int blayout, size_t dstoff) {
    const int z = blockIdx.y, ch = blockIdx.x, tid = threadIdx.x;
    const float* S = src + (size_t)z * srcZ;
    uint32_t* dst = g_wpk + dstoff + ((size_t)z * gridDim.x + ch) * 4096;
#pragma unroll
    for (int it = 0; it < 16; it++) {
        const int w = tid * 16 + it;
        const int g = w >> 6;
        const int sn = g & 7, wnkq = g >> 3;
        const int kq = wnkq & 1, wn = wnkq >> 1;
        const int rem = w & 63;
        const int r = rem & 1, lf = rem >> 1;
        const int quad = lf >> 2, four = lf & 3;
        const int k = ch * 32 + kq * 16 + r * 8 + four * 2;
        const int c = wn * 64 + sn * 8 + quad;
        const float v0 = blayout ? S[(size_t)c * ldw + k]     : S[(size_t)k * ldw + c];
        const float v1 = blayout ? S[(size_t)c * ldw + k + 1] : S[(size_t)(k + 1) * ldw + c];
        dst[w] = f2h2(v0, v1);
    }
}

// ======== fp16 m16n8k16 GEMM: C = A[M,K] @ Bpacked  (CTA 128x256) =========
// EPI 0: none. 1: +bias. 2: relu(+bias).
// ASRC 0: Ap arg. 1: g_x1. 2: g_x2.   CDST 0: Cp arg. 1: g_h. 2: g_h2. 3: g_x2.
// TERMS 2: hi/lo A split (~21-bit). TERMS 1: plain fp16-rn.
// NSPLIT>1: split-K over blockIdx.z, atomic epilogue, bias on ks==0 only.
template <int EPI, int ASRC, int CDST, int TERMS, int NSPLIT>
__global__ void __launch_bounds__(512, 1) k_gemm_f16(
    const float* __restrict__ Ap, int lda, size_t strideA, int a_shift,
    size_t bpk_off, int b_mask, int bchunks,
    float* __restrict__ Cp, int ldc, size_t strideC,
    const float* __restrict__ bias, int K)
{
    constexpr int GA0 = 0;                           // hi A: 2 x 2048
    constexpr int GL0 = 4096;                        // lo A (TERMS 2)
    constexpr int GB0 = (TERMS == 2) ? 8192 : 4096;  // B: 2 x 4096

    extern __shared__ uint32_t smw[];
    const int tid = threadIdx.x;
    const int lane = tid & 31, wid = tid >> 5;
    const int wm = wid >> 2, wn = wid & 3;
    const int quad = lane >> 2, four = lane & 3;
    const int z = blockIdx.z;
    const int i0 = blockIdx.x * 128;

    const float* Abase = (ASRC == 0) ? Ap : (ASRC == 1) ? g_x1 : g_x2;
    float*       Cbase = (CDST == 0) ? Cp : (CDST == 1) ? g_h
                       : (CDST == 2) ? g_h2 : g_x2;

    int zb = z, ks = 0;
    if (NSPLIT > 1) { zb = z / NSPLIT; ks = z % NSPLIT; }
    const int kb0 = (NSPLIT > 1) ? ks * (K / NSPLIT) : 0;
    const int ch0 = kb0 / 32;
    const int CH  = (K / NSPLIT) >> 5;

    const float* A = Abase + (size_t)((NSPLIT > 1) ? zb : (z >> a_shift)) * strideA;
    const uint32_t* Bpk = g_wpk + bpk_off
        + (size_t)(((NSPLIT > 1) ? zb : z) & b_mask) * bchunks * 4096;
    float* C = Cbase + (size_t)zb * strideC;

    // A staging ids: 512 = swm(4) x skq(2) x ssmi(2) x sln(32)  (proven R14)
    const int swm  = tid >> 7;
    const int skq  = (tid >> 6) & 1;
    const int ssmi = (tid >> 5) & 1;
    const int sln  = tid & 31;
    const int sq = sln >> 2, sf = sln & 3;
    const int R0 = i0 + swm * 32 + ssmi * 16 + sq;
    const int c0 = skq * 16 + sf * 2;
    const float* rowA = A + (size_t)R0 * lda;
    const float* rowB = A + (size_t)(R0 + 8) * lda;

    float2 aA0, aA8, aB0, aB8;
    uint4 hb0, hb1;
    auto loadA = [&](int kb) {
        aA0 = *(const float2*)(rowA + kb + c0);
        aA8 = *(const float2*)(rowA + kb + c0 + 8);
        aB0 = *(const float2*)(rowB + kb + c0);
        aB8 = *(const float2*)(rowB + kb + c0 + 8);
    };
    auto loadB = [&](int ch) {
        const uint4* src = (const uint4*)(Bpk + (size_t)ch * 4096) + tid * 2;
        hb0 = src[0];
        hb1 = src[1];
    };
    auto store_chunk = [&](int s) {
        uint4 whi, wlo;
        split2(aA0.x, aA0.y, whi.x, wlo.x);
        split2(aB0.x, aB0.y, whi.y, wlo.y);
        split2(aA8.x, aA8.y, whi.z, wlo.z);
        split2(aB8.x, aB8.y, whi.w, wlo.w);
        const int ai = ((swm * 2 + skq) * 2 + ssmi) * 128 + sln * 4;
        *(uint4*)(smw + GA0 + s * 2048 + ai) = whi;
        if constexpr (TERMS == 2)
            *(uint4*)(smw + GL0 + s * 2048 + ai) = wlo;
        uint4* bd = (uint4*)(smw + GB0 + s * 4096) + tid * 2;
        bd[0] = hb0;
        bd[1] = hb1;
    };

    loadA(kb0);
    loadB(ch0);
    store_chunk(0);
    __syncthreads();

    float acc[2][8][4] = {};

    for (int k = 0; k < CH; k++) {
        const int s = k & 1;
        if (k + 1 < CH) {
            loadA(kb0 + (k + 1) * 32);
            loadB(ch0 + k + 1);
        }
        const uint32_t* Ab = smw + GA0 + s * 2048;
        const uint32_t* Bb = smw + GB0 + s * 4096;
#pragma unroll
        for (int kq = 0; kq < 2; kq++) {
            uint4 aw[2];
            aw[0] = *(const uint4*)(Ab + ((wm * 2 + kq) * 2 + 0) * 128 + lane * 4);
            aw[1] = *(const uint4*)(Ab + ((wm * 2 + kq) * 2 + 1) * 128 + lane * 4);
            if constexpr (TERMS == 2) {
                const uint32_t* Al = smw + GL0 + s * 2048;
                uint4 al[2];
                al[0] = *(const uint4*)(Al + ((wm * 2 + kq) * 2 + 0) * 128 + lane * 4);
                al[1] = *(const uint4*)(Al + ((wm * 2 + kq) * 2 + 1) * 128 + lane * 4);
#pragma unroll
                for (int sn = 0; sn < 8; sn++) {
                    const uint2 bw = *(const uint2*)(Bb + ((wn * 2 + kq) * 8 + sn) * 64 + lane * 2);
                    mma_f16(acc[0][sn], (const uint32_t*)&aw[0], bw.x, bw.y);
                    mma_f16(acc[1][sn], (const uint32_t*)&aw[1], bw.x, bw.y);
                    mma_f16(acc[0][sn], (const uint32_t*)&al[0], bw.x, bw.y);
                    mma_f16(acc[1][sn], (const uint32_t*)&al[1], bw.x, bw.y);
                }
            } else {
#pragma unroll
                for (int sn = 0; sn < 8; sn++) {
                    const uint2 bw = *(const uint2*)(Bb + ((wn * 2 + kq) * 8 + sn) * 64 + lane * 2);
                    mma_f16(acc[0][sn], (const uint32_t*)&aw[0], bw.x, bw.y);
                    mma_f16(acc[1][sn], (const uint32_t*)&aw[1], bw.x, bw.y);
                }
            }
        }
        if (k + 1 < CH) store_chunk(s ^ 1);
        __syncthreads();
    }

    const bool addb = (EPI >= 1) && (ks == 0);
#pragma unroll
    for (int smi = 0; smi < 2; smi++) {
#pragma unroll
        for (int sn = 0; sn < 8; sn++) {
            const int r0  = i0 + wm * 32 + smi * 16 + quad;
            const int col = wn * 64 + sn * 8 + (four << 1);
            const float* c = acc[smi][sn];
            float2 v0 = {c[0], c[1]}, v1 = {c[2], c[3]};
            if (addb) {
                const float2 bb = *(const float2*)(bias + col);
                v0.x += bb.x; v0.y += bb.y;
                v1.x += bb.x; v1.y += bb.y;
            }
            if (EPI == 2) {
                v0.x = fmaxf(v0.x, 0.f); v0.y = fmaxf(v0.y, 0.f);
                v1.x = fmaxf(v1.x, 0.f); v1.y = fmaxf(v1.y, 0.f);
            }
            if constexpr (NSPLIT > 1) {
                float* d0 = C + (size_t)r0 * ldc + col;
                float* d1 = C + (size_t)(r0 + 8) * ldc + col;
                atomicAdd(d0,     v0.x); atomicAdd(d0 + 1, v0.y);
                atomicAdd(d1,     v1.x); atomicAdd(d1 + 1, v1.y);
            } else {
                *(float2*)(C + (size_t)r0 * ldc + col)       = v0;
                *(float2*)(C + (size_t)(r0 + 8) * ldc + col) = v1;
            }
        }
    }
}

// ======== fp16 m16n8k16 attention (verbatim R14 — proven) =================
template <int MODE, int S>
__global__ void __launch_bounds__(512, 1) k_attn_f16(const float* __restrict__ adj) {
    constexpr int CH = NCHUNK / S;
    extern __shared__ uint32_t smw[];
    float* s1s = (float*)(smw + AT_S1);
    float* rzs = (float*)(smw + AT_RZ);

    const int tid = threadIdx.x;
    const int lane = tid & 31, wid = tid >> 5;
    const int wm = wid >> 2, wn = wid & 3;
    const int quad = lane >> 2, four = lane & 3;
    const int bh = blockIdx.y;
    const int b  = MODE ? bh : (bh >> 3);
    const int i0 = blockIdx.x * 128;
    const int jbase = blockIdx.z * (N / S);
    const int ch0 = jbase / 32;

    const float* s1g = MODE ? g_s1b : g_s1;
    const float* s2g = MODE ? g_s2b : g_s2;
    const float* rzg = MODE ? g_rzb : g_rz;
    const uint32_t* hpk = (MODE ? g_h2pk : g_hpk) + (size_t)bh * NCH32 * 4096;
    const float* s2p = s2g + bh * N;

    if (tid < 128) {
        const int r = bh * N + i0 + tid;
        s1s[tid] = s1g[r]; rzs[tid] = rzg[r];
    }
    __syncthreads();

    const int swm  = tid >> 7;
    const int skq  = (tid >> 6) & 1;
    const int ssmi = (tid >> 5) & 1;
    const int sln  = tid & 31;
    const int sq = sln >> 2, sf = sln & 3;
    const int R0 = i0 + swm * 32 + ssmi * 16 + sq;
    const int c0 = skq * 16 + sf * 2;
    const float s1a = s1s[R0 - i0],     rza = rzs[R0 - i0];
    const float s1b = s1s[R0 - i0 + 8], rzb = rzs[R0 - i0 + 8];
    const float* adjA = adj + (size_t)(b * N + R0) * N;
    const float* adjB = adjA + (size_t)8 * N;

    float2 aA0, aA8, aB0, aB8, s2lo, s2hi;
    uint4 hb0, hb1;
    auto loadA = [&](int j0) {
        aA0 = *(const float2*)(adjA + j0 + c0);
        aA8 = *(const float2*)(adjA + j0 + c0 + 8);
        aB0 = *(const float2*)(adjB + j0 + c0);
        aB8 = *(const float2*)(adjB + j0 + c0 + 8);
        s2lo = *(const float2*)(s2p + j0 + c0);
        s2hi = *(const float2*)(s2p + j0 + c0 + 8);
    };
    auto loadB = [&](int ch) {
        const uint4* src = (const uint4*)(hpk + (size_t)ch * 4096) + tid * 2;
        hb0 = src[0];
        hb1 = src[1];
    };
    auto pval = [&](float a, float s1v, float rz, float s2v) -> float {
        return (a > 0.f) ? __expf(lrelu(s1v + s2v)) * rz : 0.f;
    };
    auto store_chunk = [&](int s) {
        const float p00 = pval(aA0.x, s1a, rza, s2lo.x);
        const float p01 = pval(aA0.y, s1a, rza, s2lo.y);
        const float p02 = pval(aA8.x, s1a, rza, s2hi.x);
        const float p03 = pval(aA8.y, s1a, rza, s2hi.y);
        const float p10 = pval(aB0.x, s1b, rzb, s2lo.x);
        const float p11 = pval(aB0.y, s1b, rzb, s2lo.y);
        const float p12 = pval(aB8.x, s1b, rzb, s2hi.x);
        const float p13 = pval(aB8.y, s1b, rzb, s2hi.y);
        uint4 w;
        w.x = f2h2(p00, p01);
        w.y = f2h2(p10, p11);
        w.z = f2h2(p02, p03);
        w.w = f2h2(p12, p13);
        *(uint4*)(smw + AT_A0 + s * 2048 + (((swm * 2 + skq) * 2 + ssmi) * 128 + sln * 4)) = w;
        uint4* bd = (uint4*)(smw + AT_B0 + s * 4096) + tid * 2;
        bd[0] = hb0;
        bd[1] = hb1;
    };

    loadA(jbase);
    loadB(ch0);
    store_chunk(0);
    __syncthreads();

    float acc[2][8][4] = {};

    for (int k = 0; k < CH; k++) {
        const int s = k & 1;
        if (k + 1 < CH) {
            loadA(jbase + (k + 1) * KC);
            loadB(ch0 + k + 1);
        }
        const uint32_t* Ab = smw + AT_A0 + s * 2048;
        const uint32_t* Bb = smw + AT_B0 + s * 4096;
#pragma unroll
        for (int kq = 0; kq < 2; kq++) {
            uint4 aw[2];
            aw[0] = *(const uint4*)(Ab + ((wm * 2 + kq) * 2 + 0) * 128 + lane * 4);
            aw[1] = *(const uint4*)(Ab + ((wm * 2 + kq) * 2 + 1) * 128 + lane * 4);
#pragma unroll
            for (int sn = 0; sn < 8; sn++) {
                const uint2 bw = *(const uint2*)(Bb + ((wn * 2 + kq) * 8 + sn) * 64 + lane * 2);
                mma_f16(acc[0][sn], (const uint32_t*)&aw[0], bw.x, bw.y);
                mma_f16(acc[1][sn], (const uint32_t*)&aw[1], bw.x, bw.y);
            }
        }
        if (k + 1 < CH) store_chunk(s ^ 1);
        __syncthreads();
    }

#pragma unroll
    for (int smi = 0; smi < 2; smi++) {
#pragma unroll
        for (int sn = 0; sn < 8; sn++) {
            const int row0 = i0 + wm * 32 + smi * 16 + quad;
            const int col  = wn * 64 + sn * 8 + (four << 1);
            const float* c = acc[smi][sn];
            if (MODE == 0) {
                float* d0 = g_x1 + ((size_t)b * N + row0) * HO + (bh & 7) * O + col;
                float* d1 = d0 + (size_t)8 * HO;
                float2 v0 = {eluf(c[0]), eluf(c[1])};
                float2 v1 = {eluf(c[2]), eluf(c[3])};
                *(float2*)d0 = v0;
                *(float2*)d1 = v1;
            } else {
                float* d0 = g_x2 + ((size_t)b * N + row0) * O + col;
                float* d1 = d0 + (size_t)8 * O;
                atomicAdd(d0,     c[0]); atomicAdd(d0 + 1, c[1]);
                atomicAdd(d1,     c[2]); atomicAdd(d1 + 1, c[3]);
            }
        }
    }
}

// ---------------- Kernel 2: s1/s2 dots (multi-head) -----------------------
__global__ void k_sdots_multi(const float* __restrict__ ah) {
    const int gt = blockIdx.x * 256 + threadIdx.x;
    const int gw = gt >> 5, lane = gt & 31;
    const int hh = (gw / N) & 7;
    const int b  = gw / (N * H);
    const int n  = gw % N;
    const float4* hr = (const float4*)(g_h + (size_t)gw * O);
    const float4* a1 = (const float4*)(ah + (size_t)hh * 2 * O);
    const float4* a2 = a1 + O / 4;
    float d1 = 0.f, d2 = 0.f;
#pragma unroll
    for (int t = 0; t < 2; t++) {
        const int idx = lane * 2 + t;
        const float4 hv = hr[idx], av = a1[idx], bv = a2[idx];
        d1 += hv.x * av.x + hv.y * av.y + hv.z * av.z + hv.w * av.w;
        d2 += hv.x * bv.x + hv.y * bv.y + hv.z * bv.z + hv.w * bv.w;
    }
#pragma unroll
    for (int s = 16; s; s >>= 1) {
        d1 += __shfl_xor_sync(0xffffffffu, d1, s);
        d2 += __shfl_xor_sync(0xffffffffu, d2, s);
    }
    if (lane == 0) {
        g_s1[gw] = d1;
        g_s2[gw] = d2;
        g_s2t[((size_t)b * N + n) * H + hh] = d2;
    }
}

// ---------------- Kernel 3: softmax Z (no max; e bounded) -----------------
__global__ void k_stats_multi(const float* __restrict__ adj) {
    const int bi = blockIdx.x;
    const int b  = bi >> 11;
    const int i  = bi & (N - 1);
    const int tid = threadIdx.x, lane = tid & 31, wid = tid >> 5;

    float s1v[H];
#pragma unroll
    for (int hh = 0; hh < H; hh++) s1v[hh] = g_s1[(b * H + hh) * N + i];
    float zs[H];
#pragma unroll
    for (int hh = 0; hh < H; hh++) zs[hh] = 0.f;

    const float* arow = adj + (size_t)bi * N;
    for (int j = tid; j < N; j += 256) {
        if (arow[j] > 0.f) {
            const float4* s2p = (const float4*)(g_s2t + (size_t)(b * N + j) * H);
            const float4 sa = s2p[0], sb = s2p[1];
            const float sv[8] = {sa.x, sa.y, sa.z, sa.w, sb.x, sb.y, sb.z, sb.w};
#pragma unroll
            for (int hh = 0; hh < H; hh++)
                zs[hh] += __expf(lrelu(s1v[hh] + sv[hh]));
        }
    }
#pragma unroll
    for (int hh = 0; hh < H; hh++)
        for (int s = 16; s; s >>= 1)
            zs[hh] += __shfl_xor_sync(0xffffffffu, zs[hh], s);
    __shared__ float smz[8][8];
    if (lane == 0) {
#pragma unroll
        for (int hh = 0; hh < H; hh++) smz[wid][hh] = zs[hh];
    }
    __syncthreads();
    if (tid < 8) {
        float zt = 0.f;
#pragma unroll
        for (int w = 0; w < 8; w++) zt += smz[w][tid];
        g_rz[(b * H + tid) * N + i] = 1.f / zt;
    }
}

// ---------------- Kernel 6: single-head s dots ----------------------------
__global__ void k_sdots_single(const float* __restrict__ aout) {
    const int gt = blockIdx.x * 256 + threadIdx.x;
    const int gw = gt >> 5, lane = gt & 31;
    const float4* hr = (const float4*)(g_h2 + (size_t)gw * O);
    const float4* a1 = (const float4*)(aout);
    const float4* a2 = (const float4*)(aout + O);
    float d1 = 0.f, d2 = 0.f;
#pragma unroll
    for (int t = 0; t < 2; t++) {
        const int idx = lane * 2 + t;
        const float4 hv = hr[idx], av = a1[idx], bv = a2[idx];
        d1 += hv.x * av.x + hv.y * av.y + hv.z * av.z + hv.w * av.w;
        d2 += hv.x * bv.x + hv.y * bv.y + hv.z * bv.z + hv.w * bv.w;
    }
#pragma unroll
    for (int s = 16; s; s >>= 1) {
        d1 += __shfl_xor_sync(0xffffffffu, d1, s);
        d2 += __shfl_xor_sync(0xffffffffu, d2, s);
    }
    if (lane == 0) { g_s1b[gw] = d1; g_s2b[gw] = d2; }
}

// ---------------- Kernel 7: single-head softmax Z -------------------------
__global__ void k_stats_single(const float* __restrict__ adj) {
    const int bi = blockIdx.x;
    const int b  = bi >> 11;
    const int tid = threadIdx.x, lane = tid & 31, wid = tid >> 5;
    const float s1v = g_s1b[bi];
    const float* arow = adj + (size_t)bi * N;
    float zs = 0.f;
    for (int j = tid; j < N; j += 256) {
        if (arow[j] > 0.f)
            zs += __expf(lrelu(s1v + g_s2b[b * N + j]));
    }
    for (int s = 16; s; s >>= 1)
        zs += __shfl_xor_sync(0xffffffffu, zs, s);
    __shared__ float smz[8];
    if (lane == 0) smz[wid] = zs;
    __syncthreads();
    if (tid == 0) {
        float zt = 0.f;
#pragma unroll
        for (int w = 0; w < 8; w++) zt += smz[w];
        g_rzb[bi] = 1.f / zt;
    }
}

// ---------------- launch --------------------------------------------------
extern "C" void kernel_launch(void* const* d_in, const int* in_sizes, int n_in,
                              void* d_out, int out_size) {
    const float* x       = (const float*)d_in[0];
    const float* adj     = (const float*)d_in[1];
    const float* W_heads = (const float*)d_in[3];
    const float* a_heads = (const float*)d_in[4];
    const float* W_out   = (const float*)d_in[5];
    const float* a_out   = (const float*)d_in[6];
    const float* W_lin   = (const float*)d_in[7];
    const float* b_lin   = (const float*)d_in[8];
    const float* W_ln    = (const float*)d_in[9];
    const float* b_ln    = (const float*)d_in[10];
    float* out = (float*)d_out;

    cudaFuncSetAttribute(k_attn_f16<0, 1>, cudaFuncAttributeMaxDynamicSharedMemorySize, SMEM_ATTN_BYTES);
    cudaFuncSetAttribute(k_attn_f16<1, 4>, cudaFuncAttributeMaxDynamicSharedMemorySize, SMEM_ATTN_BYTES);
    cudaFuncSetAttribute(k_gemm_f16<0, 0, 1, 2, 1>, cudaFuncAttributeMaxDynamicSharedMemorySize, SMEM_G2_BYTES);
    cudaFuncSetAttribute(k_gemm_f16<0, 1, 2, 1, 4>, cudaFuncAttributeMaxDynamicSharedMemorySize, SMEM_G1_BYTES);
    cudaFuncSetAttribute(k_gemm_f16<1, 1, 3, 1, 4>, cudaFuncAttributeMaxDynamicSharedMemorySize, SMEM_G1_BYTES);
    cudaFuncSetAttribute(k_gemm_f16<2, 2, 0, 1, 1>, cudaFuncAttributeMaxDynamicSharedMemorySize, SMEM_G1_BYTES);

    // zero atomic targets; pack all weights into fragment layout
    k_zero<<<1024, 256>>>();
    k_packB<<<dim3(F / 32, H), 256>>>(W_heads, (size_t)F * O, O, 0, OFF_WH);
    k_packB<<<dim3(HO / 32, 1), 256>>>(W_out, 0, O, 0, OFF_WOUT);
    k_packB<<<dim3(HO / 32, 1), 256>>>(W_lin, 0, HO, 1, OFF_WLIN);
    k_packB<<<dim3(O / 32, 1), 256>>>(W_ln, 0, O, 1, OFF_WLN);

    // layer-0 projection: h[bh] = x[b] @ W_heads[h]  (2-term fp16 split)
    k_gemm_f16<0, 0, 1, 2, 1><<<dim3(16, 1, B * H), 512, SMEM_G2_BYTES>>>(
        x, F, (size_t)N * F, 3,
        OFF_WH, 7, F / 32,
        nullptr, O, (size_t)N * O,
        nullptr, F);
    k_sdots_multi <<<(B * H * N) / 8, 256>>>(a_heads);
    k_pack<0>     <<<dim3(NCH32, B * H), 256>>>();
    k_stats_multi <<<B * N, 256>>>(adj);
    k_attn_f16<0, 1><<<dim3(N / 128, B * H, 1), 512, SMEM_ATTN_BYTES>>>(adj);
    // h2 = x1 @ W_out   (fp16, split-K4)
    k_gemm_f16<0, 1, 2, 1, 4><<<dim3(16, 1, B * 4), 512, SMEM_G1_BYTES>>>(
        nullptr, HO, (size_t)N * HO, 0,
        OFF_WOUT, 0, HO / 32,
        nullptr, O, (size_t)N * O,
        nullptr, HO);
    // x2 = x1 @ W_lin^T + b_lin   (fp16, split-K4)
    k_gemm_f16<1, 1, 3, 1, 4><<<dim3(16, 1, B * 4), 512, SMEM_G1_BYTES>>>(
        nullptr, HO, (size_t)N * HO, 0,
        OFF_WLIN, 0, HO / 32,
        nullptr, O, (size_t)N * O,
        b_lin, HO);
    k_sdots_single<<<(B * N) / 8, 256>>>(a_out);
    k_pack<1>     <<<dim3(NCH32, B), 256>>>();
    k_stats_single<<<B * N, 256>>>(adj);
    k_attn_f16<1, 4><<<dim3(N / 128, B, 4), 512, SMEM_ATTN_BYTES>>>(adj);
    // out = relu(x2 @ W_ln^T + b_ln)   (fp16)
    k_gemm_f16<2, 2, 0, 1, 1><<<dim3(32, 1, 1), 512, SMEM_G1_BYTES>>>(
        nullptr, O, 0, 0,
        OFF_WLN, 0, O / 32,
        out, O, 0,
        b_ln, O);
}